// round 1
// baseline (speedup 1.0000x reference)
#include <cuda_runtime.h>

// Problem constants
#define BB 8
#define SS 64
#define NN 256
#define FF 16
#define HH 16
#define CC 4096            // N*H
#define COLS 512           // B*S
#define KTOT 12288         // C*3
#define SP 66              // padded S (1 zero each side)
#define CSTRIDE (BB*SP)    // 528 floats per channel row in Tpad
#define ALPHA 0.2f
#define EPS 1e-5f

// Scratch (device globals; no allocations allowed)
__device__ float    g_Wh[COLS * NN * HH];     // 8 MB
__device__ float    g_f1[COLS * NN];
__device__ float    g_f2[COLS * NN];
__device__ unsigned g_mask[NN * 8];           // adj>0 bitmask, 8 words per row
__device__ float    g_Tpad[CC * CSTRIDE];     // [c][b*66 + s+1], zero-padded ends
__device__ float    g_Yt[COLS * CC];          // conv result, [col][o]

// ---------------------------------------------------------------------------
// Kernel 0: adjacency bitmask (256 rows x 8 words)
// ---------------------------------------------------------------------------
__global__ void k_mask(const float* __restrict__ adj) {
    int idx = blockIdx.x * blockDim.x + threadIdx.x;   // 2048 threads
    if (idx >= NN * 8) return;
    int i = idx >> 3;
    int w = idx & 7;
    unsigned m = 0;
#pragma unroll
    for (int b = 0; b < 32; b++) {
        if (adj[i * NN + w * 32 + b] > 0.0f) m |= (1u << b);
    }
    g_mask[idx] = m;
}

// ---------------------------------------------------------------------------
// Kernel 1: Wh = x @ W ; f1 = Wh.a1 ; f2 = Wh.a2
// grid = 512 (b*s), block = 256 (n)
// ---------------------------------------------------------------------------
__global__ void k_wh(const float* __restrict__ x, const float* __restrict__ W,
                     const float* __restrict__ a1, const float* __restrict__ a2) {
    __shared__ float sW[FF * HH];
    __shared__ float sa1[HH], sa2[HH];
    int t = threadIdx.x;
    sW[t] = W[t];                 // 256 == F*H
    if (t < HH) { sa1[t] = a1[t]; sa2[t] = a2[t]; }
    __syncthreads();

    int bs = blockIdx.x;
    const float* xr = x + (size_t)(bs * NN + t) * FF;
    float xv[FF];
#pragma unroll
    for (int f = 0; f < FF; f += 4) {
        float4 v = *(const float4*)(xr + f);
        xv[f] = v.x; xv[f + 1] = v.y; xv[f + 2] = v.z; xv[f + 3] = v.w;
    }
    float wh[HH];
#pragma unroll
    for (int h = 0; h < HH; h++) wh[h] = 0.0f;
#pragma unroll
    for (int f = 0; f < FF; f++) {
#pragma unroll
        for (int h = 0; h < HH; h++) wh[h] += xv[f] * sW[f * HH + h];
    }
    float f1 = 0.0f, f2 = 0.0f;
#pragma unroll
    for (int h = 0; h < HH; h++) { f1 += wh[h] * sa1[h]; f2 += wh[h] * sa2[h]; }

    float* whr = g_Wh + (size_t)(bs * NN + t) * HH;
#pragma unroll
    for (int h = 0; h < HH; h += 4) {
        *(float4*)(whr + h) = make_float4(wh[h], wh[h + 1], wh[h + 2], wh[h + 3]);
    }
    g_f1[bs * NN + t] = f1;
    g_f2[bs * NN + t] = f2;
}

// ---------------------------------------------------------------------------
// Kernel 2: attention softmax + spatial = attn @ Wh, scattered into Tpad
// grid = 512 (b*s), block = 256 (row i)
// ---------------------------------------------------------------------------
__global__ void k_attn() {
    __shared__ float    sWh[NN * HH];    // 16 KB
    __shared__ float    sf2[NN];
    __shared__ unsigned smask[NN * 8];   // 8 KB

    int bs = blockIdx.x;
    int t = threadIdx.x;
    int b = bs >> 6, s = bs & 63;

    for (int idx = t; idx < NN * HH; idx += 256) sWh[idx] = g_Wh[(size_t)bs * NN * HH + idx];
    sf2[t] = g_f2[bs * NN + t];
    for (int idx = t; idx < NN * 8; idx += 256) smask[idx] = g_mask[idx];
    __syncthreads();

    float f1i = g_f1[bs * NN + t];

    // pass 1: masked max
    float m = -1e30f;
#pragma unroll 1
    for (int jw = 0; jw < 8; jw++) {
        unsigned wd = smask[t * 8 + jw];
#pragma unroll
        for (int bit = 0; bit < 32; bit++) {
            float e = f1i + sf2[jw * 32 + bit];
            e = e > 0.0f ? e : ALPHA * e;
            if ((wd >> bit) & 1u) m = fmaxf(m, e);
        }
    }

    // pass 2: exp, sum, weighted accumulate
    float sum = 0.0f;
    float acc[HH];
#pragma unroll
    for (int h = 0; h < HH; h++) acc[h] = 0.0f;

#pragma unroll 1
    for (int jw = 0; jw < 8; jw++) {
        unsigned wd = smask[t * 8 + jw];
#pragma unroll
        for (int bit = 0; bit < 32; bit++) {
            int j = jw * 32 + bit;
            float e = f1i + sf2[j];
            e = e > 0.0f ? e : ALPHA * e;
            float w = ((wd >> bit) & 1u) ? __expf(e - m) : 0.0f;
            sum += w;
#pragma unroll
            for (int h = 0; h < HH; h++) acc[h] += w * sWh[j * HH + h];
        }
    }

    float inv = 1.0f / sum;
    int c0 = t * HH;
    int colo = b * SP + s + 1;
#pragma unroll
    for (int h = 0; h < HH; h++) {
        g_Tpad[(size_t)(c0 + h) * CSTRIDE + colo] = acc[h] * inv;
    }
    if (s == 0) {
#pragma unroll
        for (int h = 0; h < HH; h++) g_Tpad[(size_t)(c0 + h) * CSTRIDE + b * SP] = 0.0f;
    }
    if (s == 63) {
#pragma unroll
        for (int h = 0; h < HH; h++) g_Tpad[(size_t)(c0 + h) * CSTRIDE + b * SP + 65] = 0.0f;
    }
}

// ---------------------------------------------------------------------------
// Kernel 3: conv as GEMM. Y[o][col] = sum_{c,k} W[o][c][k] * Tpad[c][b*66+s+k]
// M=4096, Ncol=512, K=12288. 128x128 tile, BK=8, 256 threads, double buffered.
// Writes Yt[col][o] (transposed) for coalesced epilogue reads.
// ---------------------------------------------------------------------------
#define BM 128
#define BN 128
#define BKC 8
#define LDA 132   // padded to avoid smem store conflicts

__global__ __launch_bounds__(256) void k_conv(const float* __restrict__ Wt) {
    __shared__ float As[2][BKC][LDA];
    __shared__ float Bs[2][BKC][BN];

    int t = threadIdx.x;
    int oBase = blockIdx.y * BM;
    int colBase = blockIdx.x * BN;
    int tx = t & 15, ty = t >> 4;

    int aRow = t >> 1;
    int aK4 = (t & 1) * 4;
    int bKK = t >> 5;
    int bLane = t & 31;

    float acc[8][8];
#pragma unroll
    for (int i = 0; i < 8; i++)
#pragma unroll
        for (int j = 0; j < 8; j++) acc[i][j] = 0.0f;

    // prologue: tile 0 -> buffer 0
    {
        const float* ga = Wt + (size_t)(oBase + aRow) * KTOT + aK4;
        float4 av = *(const float4*)ga;
        As[0][aK4 + 0][aRow] = av.x;
        As[0][aK4 + 1][aRow] = av.y;
        As[0][aK4 + 2][aRow] = av.z;
        As[0][aK4 + 3][aRow] = av.w;

        int kkg = bKK;
        int c = kkg / 3;
        int ktap = kkg - c * 3;
        const float* gb = g_Tpad + (size_t)c * CSTRIDE + ktap;
#pragma unroll
        for (int r = 0; r < 4; r++) {
            int col = colBase + bLane + 32 * r;
            Bs[0][bKK][bLane + 32 * r] = gb[(col >> 6) * SP + (col & 63)];
        }
    }
    __syncthreads();

    int cur = 0;
    const int NIT = KTOT / BKC;   // 1536
    for (int kt = 0; kt < NIT; kt++) {
        float4 aN;
        float bN[4];
        bool has = (kt + 1) < NIT;
        if (has) {
            int kb = (kt + 1) * BKC;
            const float* ga = Wt + (size_t)(oBase + aRow) * KTOT + kb + aK4;
            aN = *(const float4*)ga;
            int kkg = kb + bKK;
            int c = kkg / 3;
            int ktap = kkg - c * 3;
            const float* gb = g_Tpad + (size_t)c * CSTRIDE + ktap;
#pragma unroll
            for (int r = 0; r < 4; r++) {
                int col = colBase + bLane + 32 * r;
                bN[r] = gb[(col >> 6) * SP + (col & 63)];
            }
        }

#pragma unroll
        for (int kk = 0; kk < BKC; kk++) {
            float4 a0 = *(const float4*)&As[cur][kk][ty * 4];
            float4 a1 = *(const float4*)&As[cur][kk][ty * 4 + 64];
            float4 b0 = *(const float4*)&Bs[cur][kk][tx * 4];
            float4 b1 = *(const float4*)&Bs[cur][kk][tx * 4 + 64];
            float av[8] = {a0.x, a0.y, a0.z, a0.w, a1.x, a1.y, a1.z, a1.w};
            float bv[8] = {b0.x, b0.y, b0.z, b0.w, b1.x, b1.y, b1.z, b1.w};
#pragma unroll
            for (int i = 0; i < 8; i++)
#pragma unroll
                for (int j = 0; j < 8; j++) acc[i][j] += av[i] * bv[j];
        }

        if (has) {
            int nxt = cur ^ 1;
            As[nxt][aK4 + 0][aRow] = aN.x;
            As[nxt][aK4 + 1][aRow] = aN.y;
            As[nxt][aK4 + 2][aRow] = aN.z;
            As[nxt][aK4 + 3][aRow] = aN.w;
#pragma unroll
            for (int r = 0; r < 4; r++) Bs[nxt][bKK][bLane + 32 * r] = bN[r];
            __syncthreads();
            cur = nxt;
        }
    }

    // epilogue: Yt[col][o], vectorized over o (rows)
#pragma unroll
    for (int jg = 0; jg < 2; jg++) {
#pragma unroll
        for (int j = 0; j < 4; j++) {
            int col = colBase + tx * 4 + jg * 64 + j;
#pragma unroll
            for (int ig = 0; ig < 2; ig++) {
                int o = oBase + ty * 4 + ig * 64;
                float4 v = make_float4(acc[ig * 4 + 0][jg * 4 + j],
                                       acc[ig * 4 + 1][jg * 4 + j],
                                       acc[ig * 4 + 2][jg * 4 + j],
                                       acc[ig * 4 + 3][jg * 4 + j]);
                *(float4*)&g_Yt[(size_t)col * CC + o] = v;
            }
        }
    }
}

// ---------------------------------------------------------------------------
// Kernel 4: bias + BN + ReLU + residual + LayerNorm(H=16)
// grid = 512 (b*s), block = 256 (n)
// ---------------------------------------------------------------------------
__global__ void k_final(const float* __restrict__ x,
                        const float* __restrict__ conv_b,
                        const float* __restrict__ bn_g, const float* __restrict__ bn_b,
                        const float* __restrict__ bn_m, const float* __restrict__ bn_v,
                        const float* __restrict__ ln_g, const float* __restrict__ ln_b,
                        float* __restrict__ out) {
    int bs = blockIdx.x, n = threadIdx.x;
    size_t base = (size_t)bs * CC + n * HH;   // identical indexing for Yt, x, out
    size_t obase = (size_t)n * HH;            // channel o = n*16+h

    float v[HH];
#pragma unroll
    for (int h = 0; h < HH; h += 4) {
        float4 y = *(const float4*)&g_Yt[base + h];
        float4 cb = *(const float4*)&conv_b[obase + h];
        float4 bm = *(const float4*)&bn_m[obase + h];
        float4 bvr = *(const float4*)&bn_v[obase + h];
        float4 bg = *(const float4*)&bn_g[obase + h];
        float4 bb = *(const float4*)&bn_b[obase + h];
        float4 xr = *(const float4*)&x[base + h];
        float yy[4] = {y.x, y.y, y.z, y.w};
        float cbv[4] = {cb.x, cb.y, cb.z, cb.w};
        float bmv[4] = {bm.x, bm.y, bm.z, bm.w};
        float bvv[4] = {bvr.x, bvr.y, bvr.z, bvr.w};
        float bgv[4] = {bg.x, bg.y, bg.z, bg.w};
        float bbv[4] = {bb.x, bb.y, bb.z, bb.w};
        float xv[4] = {xr.x, xr.y, xr.z, xr.w};
#pragma unroll
        for (int q = 0; q < 4; q++) {
            float val = yy[q] + cbv[q];
            val = (val - bmv[q]) * rsqrtf(bvv[q] + EPS) * bgv[q] + bbv[q];
            val = fmaxf(val, 0.0f);
            v[h + q] = val + xv[q];
        }
    }

    float mu = 0.0f;
#pragma unroll
    for (int h = 0; h < HH; h++) mu += v[h];
    mu *= (1.0f / HH);
    float var = 0.0f;
#pragma unroll
    for (int h = 0; h < HH; h++) { float d = v[h] - mu; var += d * d; }
    var *= (1.0f / HH);
    float is = rsqrtf(var + EPS);

#pragma unroll
    for (int h = 0; h < HH; h++) {
        out[base + h] = (v[h] - mu) * is * ln_g[h] + ln_b[h];
    }
}

// ---------------------------------------------------------------------------
extern "C" void kernel_launch(void* const* d_in, const int* in_sizes, int n_in,
                              void* d_out, int out_size) {
    const float* x      = (const float*)d_in[0];
    const float* adj    = (const float*)d_in[1];
    const float* W      = (const float*)d_in[2];
    const float* a1     = (const float*)d_in[3];
    const float* a2     = (const float*)d_in[4];
    const float* conv_w = (const float*)d_in[5];
    const float* conv_b = (const float*)d_in[6];
    const float* bn_g   = (const float*)d_in[7];
    const float* bn_b   = (const float*)d_in[8];
    const float* bn_m   = (const float*)d_in[9];
    const float* bn_v   = (const float*)d_in[10];
    const float* ln_g   = (const float*)d_in[11];
    const float* ln_b   = (const float*)d_in[12];
    float* out = (float*)d_out;

    k_mask<<<8, 256>>>(adj);
    k_wh<<<512, 256>>>(x, W, a1, a2);
    k_attn<<<512, 256>>>();
    k_conv<<<dim3(4, 32), 256>>>(conv_w);
    k_final<<<512, 256>>>(x, conv_b, bn_g, bn_b, bn_m, bn_v, ln_g, ln_b, out);
}

// round 3
// speedup vs baseline: 2.9294x; 2.9294x over previous
#include <cuda_runtime.h>
#include <cuda_bf16.h>
#include <cstdint>

// Problem constants
#define BB 8
#define SS 64
#define NN 256
#define FF 16
#define HH 16
#define CC 4096            // N*H  (= GEMM M)
#define COLS 512           // B*S  (= GEMM Ncol)
#define KTOT 12288         // C*3  (= GEMM K)
#define ALPHA 0.2f
#define EPS 1e-5f

// GEMM tiling (HMMA path)
#define BK 32                       // bf16 K per stage
#define PADB 80                     // padded row stride in bytes (40 bf16)
#define TILEB (128 * PADB)          // 10240 B per tile
#define STAGEB (4 * TILEB)          // Ahi, Alo, Bhi, Blo
#define NSTAGE 3
#define NIT (KTOT / BK)             // 384
#define SMEM_DYN (NSTAGE * STAGEB)  // 122880

// ---------------- device scratch (no allocations allowed) -------------------
__device__ float         g_Wh[COLS * NN * HH];
__device__ float         g_f1[COLS * NN];
__device__ float         g_f2[COLS * NN];
__device__ unsigned      g_mask[NN * 8];
__device__ float         g_S[(size_t)COLS * CC];        // spatial [col][c]
__device__ __nv_bfloat16 g_Ahi[(size_t)CC * KTOT];
__device__ __nv_bfloat16 g_Alo[(size_t)CC * KTOT];
__device__ __nv_bfloat16 g_Bhi[(size_t)COLS * KTOT];
__device__ __nv_bfloat16 g_Blo[(size_t)COLS * KTOT];
__device__ float         g_Yt[(size_t)COLS * CC];       // conv out [col][o]

// ---------------- PTX helpers ----------------------------------------------
__device__ __forceinline__ void cp16(unsigned dst, const void* src) {
    asm volatile("cp.async.cg.shared.global [%0], [%1], 16;" :: "r"(dst), "l"(src) : "memory");
}
__device__ __forceinline__ void cp_commit() {
    asm volatile("cp.async.commit_group;" ::: "memory");
}
__device__ __forceinline__ unsigned lds32(unsigned a) {
    unsigned v;
    asm("ld.shared.b32 %0, [%1];" : "=r"(v) : "r"(a));
    return v;
}
__device__ __forceinline__ void mma16816(float* d, const unsigned* a, const unsigned* b) {
    asm volatile(
        "mma.sync.aligned.m16n8k16.row.col.f32.bf16.bf16.f32 "
        "{%0,%1,%2,%3}, {%4,%5,%6,%7}, {%8,%9}, {%0,%1,%2,%3};"
        : "+f"(d[0]), "+f"(d[1]), "+f"(d[2]), "+f"(d[3])
        : "r"(a[0]), "r"(a[1]), "r"(a[2]), "r"(a[3]), "r"(b[0]), "r"(b[1]));
}

// ---------------------------------------------------------------------------
// Kernel 0: adjacency bitmask
// ---------------------------------------------------------------------------
__global__ void k_mask(const float* __restrict__ adj) {
    int idx = blockIdx.x * blockDim.x + threadIdx.x;
    if (idx >= NN * 8) return;
    int i = idx >> 3, w = idx & 7;
    unsigned m = 0;
#pragma unroll
    for (int b = 0; b < 32; b++)
        if (adj[i * NN + w * 32 + b] > 0.0f) m |= (1u << b);
    g_mask[idx] = m;
}

// ---------------------------------------------------------------------------
// Kernel 1: Wh = x @ W ; f1 = Wh.a1 ; f2 = Wh.a2
// ---------------------------------------------------------------------------
__global__ void k_wh(const float* __restrict__ x, const float* __restrict__ W,
                     const float* __restrict__ a1, const float* __restrict__ a2) {
    __shared__ float sW[FF * HH];
    __shared__ float sa1[HH], sa2[HH];
    int t = threadIdx.x;
    sW[t] = W[t];
    if (t < HH) { sa1[t] = a1[t]; sa2[t] = a2[t]; }
    __syncthreads();

    int bs = blockIdx.x;
    const float* xr = x + (size_t)(bs * NN + t) * FF;
    float xv[FF];
#pragma unroll
    for (int f = 0; f < FF; f += 4) {
        float4 v = *(const float4*)(xr + f);
        xv[f] = v.x; xv[f + 1] = v.y; xv[f + 2] = v.z; xv[f + 3] = v.w;
    }
    float wh[HH];
#pragma unroll
    for (int h = 0; h < HH; h++) wh[h] = 0.0f;
#pragma unroll
    for (int f = 0; f < FF; f++)
#pragma unroll
        for (int h = 0; h < HH; h++) wh[h] += xv[f] * sW[f * HH + h];

    float f1 = 0.0f, f2 = 0.0f;
#pragma unroll
    for (int h = 0; h < HH; h++) { f1 += wh[h] * sa1[h]; f2 += wh[h] * sa2[h]; }

    float* whr = g_Wh + (size_t)(bs * NN + t) * HH;
#pragma unroll
    for (int h = 0; h < HH; h += 4)
        *(float4*)(whr + h) = make_float4(wh[h], wh[h + 1], wh[h + 2], wh[h + 3]);
    g_f1[bs * NN + t] = f1;
    g_f2[bs * NN + t] = f2;
}

// ---------------------------------------------------------------------------
// Kernel 2: attention softmax + spatial = attn @ Wh -> g_S[col][c]
// ---------------------------------------------------------------------------
__global__ void k_attn() {
    __shared__ float    sWh[NN * HH];
    __shared__ float    sf2[NN];
    __shared__ unsigned smask[NN * 8];

    int bs = blockIdx.x;
    int t = threadIdx.x;

    for (int idx = t; idx < NN * HH; idx += 256) sWh[idx] = g_Wh[(size_t)bs * NN * HH + idx];
    sf2[t] = g_f2[bs * NN + t];
    for (int idx = t; idx < NN * 8; idx += 256) smask[idx] = g_mask[idx];
    __syncthreads();

    float f1i = g_f1[bs * NN + t];

    float m = -1e30f;
#pragma unroll 1
    for (int jw = 0; jw < 8; jw++) {
        unsigned wd = smask[t * 8 + jw];
#pragma unroll
        for (int bit = 0; bit < 32; bit++) {
            float e = f1i + sf2[jw * 32 + bit];
            e = e > 0.0f ? e : ALPHA * e;
            if ((wd >> bit) & 1u) m = fmaxf(m, e);
        }
    }

    float sum = 0.0f;
    float acc[HH];
#pragma unroll
    for (int h = 0; h < HH; h++) acc[h] = 0.0f;

#pragma unroll 1
    for (int jw = 0; jw < 8; jw++) {
        unsigned wd = smask[t * 8 + jw];
#pragma unroll
        for (int bit = 0; bit < 32; bit++) {
            int j = jw * 32 + bit;
            float e = f1i + sf2[j];
            e = e > 0.0f ? e : ALPHA * e;
            float w = ((wd >> bit) & 1u) ? __expf(e - m) : 0.0f;
            sum += w;
#pragma unroll
            for (int h = 0; h < HH; h++) acc[h] += w * sWh[j * HH + h];
        }
    }

    float inv = 1.0f / sum;
    float* so = g_S + (size_t)bs * CC + t * HH;
#pragma unroll
    for (int h = 0; h < HH; h += 4)
        *(float4*)(so + h) = make_float4(acc[h] * inv, acc[h + 1] * inv,
                                         acc[h + 2] * inv, acc[h + 3] * inv);
}

// ---------------------------------------------------------------------------
// Kernel 3a: split conv weights fp32 -> (bf16 hi, bf16 lo)
// ---------------------------------------------------------------------------
__global__ void k_splitw(const float* __restrict__ w) {
    size_t i = ((size_t)blockIdx.x * 256 + threadIdx.x) * 4;
    float4 v = *(const float4*)(w + i);
    float vv[4] = {v.x, v.y, v.z, v.w};
    __nv_bfloat16 hb[4], lb[4];
#pragma unroll
    for (int q = 0; q < 4; q++) {
        hb[q] = __float2bfloat16(vv[q]);
        lb[q] = __float2bfloat16(vv[q] - __bfloat162float(hb[q]));
    }
    *reinterpret_cast<uint2*>(g_Ahi + i) = *reinterpret_cast<uint2*>(hb);
    *reinterpret_cast<uint2*>(g_Alo + i) = *reinterpret_cast<uint2*>(lb);
}

// ---------------------------------------------------------------------------
// Kernel 3b: build B (K-major, [col][c*3+tap]) in split bf16 from g_S.
// ---------------------------------------------------------------------------
__global__ void k_buildB() {
    int col = blockIdx.x;           // 0..511
    int s = col & 63;
    for (int c = threadIdx.x; c < CC; c += 256) {
        float vm = (s > 0)  ? g_S[(size_t)(col - 1) * CC + c] : 0.0f;
        float v0 =            g_S[(size_t)col * CC + c];
        float vp = (s < 63) ? g_S[(size_t)(col + 1) * CC + c] : 0.0f;
        float t3[3] = {vm, v0, vp};
        size_t base = (size_t)col * KTOT + 3 * (size_t)c;
#pragma unroll
        for (int tap = 0; tap < 3; tap++) {
            __nv_bfloat16 h = __float2bfloat16(t3[tap]);
            __nv_bfloat16 l = __float2bfloat16(t3[tap] - __bfloat162float(h));
            g_Bhi[base + tap] = h;
            g_Blo[base + tap] = l;
        }
    }
}

// ---------------------------------------------------------------------------
// Kernel 4: HMMA 3xBF16 GEMM. D[o][col] = A[o][:] . B[col][:]
// 128x128 CTA tile, BK=32, 3-stage cp.async, 8 warps of m32n64.
// ---------------------------------------------------------------------------
__device__ __forceinline__ void issue_stage(unsigned sb, int kb, int t,
                                            const __nv_bfloat16* aHi,
                                            const __nv_bfloat16* aLo,
                                            const __nv_bfloat16* bHi,
                                            const __nv_bfloat16* bLo) {
    const __nv_bfloat16* srcs[4] = {aHi, aLo, bHi, bLo};
#pragma unroll
    for (int tile = 0; tile < 4; tile++) {
        const __nv_bfloat16* src = srcs[tile];
#pragma unroll
        for (int j = 0; j < 2; j++) {
            int c = j * 256 + t;            // 0..511
            int row = c >> 2;
            int col16 = c & 3;
            unsigned dst = sb + tile * TILEB + row * PADB + col16 * 16;
            cp16(dst, src + (size_t)row * KTOT + kb + col16 * 8);
        }
    }
    cp_commit();
}

__global__ __launch_bounds__(256, 1) void k_conv_mma() {
    extern __shared__ __align__(128) char smem[];
    unsigned sbase = (unsigned)__cvta_generic_to_shared(smem);

    int t = threadIdx.x;
    int wid = t >> 5;
    int l = t & 31;
    int l4 = l >> 2, lm4 = l & 3;
    int wm = wid & 3;          // 4 warps along M
    int wn = wid >> 2;         // 2 warps along N
    int colBase = blockIdx.x * 128;
    int oBase = blockIdx.y * 128;

    const __nv_bfloat16* aHi = g_Ahi + (size_t)oBase * KTOT;
    const __nv_bfloat16* aLo = g_Alo + (size_t)oBase * KTOT;
    const __nv_bfloat16* bHi = g_Bhi + (size_t)colBase * KTOT;
    const __nv_bfloat16* bLo = g_Blo + (size_t)colBase * KTOT;

    float d[2][8][4];
#pragma unroll
    for (int mt = 0; mt < 2; mt++)
#pragma unroll
        for (int nt = 0; nt < 8; nt++)
#pragma unroll
            for (int q = 0; q < 4; q++) d[mt][nt][q] = 0.0f;

    // prologue
    issue_stage(sbase, 0, t, aHi, aLo, bHi, bLo);
    issue_stage(sbase + STAGEB, BK, t, aHi, aLo, bHi, bLo);

    // per-warp fragment base addresses (within a stage)
    unsigned aOff = (unsigned)((wm * 32 + l4) * PADB + lm4 * 4);
    unsigned bOff = (unsigned)(2 * TILEB + (wn * 64 + l4) * PADB + lm4 * 4);

    for (int kt = 0; kt < NIT; kt++) {
        asm volatile("cp.async.wait_group 1;" ::: "memory");
        __syncthreads();

        if (kt + 2 < NIT)
            issue_stage(sbase + (unsigned)((kt + 2) % 3) * STAGEB, (kt + 2) * BK,
                        t, aHi, aLo, bHi, bLo);
        else
            cp_commit();

        unsigned sb = sbase + (unsigned)(kt % 3) * STAGEB;
        unsigned aB = sb + aOff;
        unsigned bB = sb + bOff;

#pragma unroll
        for (int ks = 0; ks < 2; ks++) {
            unsigned kO = ks * 32;   // 16 bf16 = 32 B
            unsigned ah[2][4], al[2][4];
#pragma unroll
            for (int mt = 0; mt < 2; mt++) {
                unsigned a0 = aB + mt * (16 * PADB) + kO;
                ah[mt][0] = lds32(a0);
                ah[mt][1] = lds32(a0 + 8 * PADB);
                ah[mt][2] = lds32(a0 + 16);
                ah[mt][3] = lds32(a0 + 8 * PADB + 16);
                unsigned a1 = a0 + TILEB;
                al[mt][0] = lds32(a1);
                al[mt][1] = lds32(a1 + 8 * PADB);
                al[mt][2] = lds32(a1 + 16);
                al[mt][3] = lds32(a1 + 8 * PADB + 16);
            }
            unsigned bh[8][2], bl[8][2];
#pragma unroll
            for (int nt = 0; nt < 8; nt++) {
                unsigned b0 = bB + nt * (8 * PADB) + kO;
                bh[nt][0] = lds32(b0);
                bh[nt][1] = lds32(b0 + 16);
                unsigned b1 = b0 + TILEB;
                bl[nt][0] = lds32(b1);
                bl[nt][1] = lds32(b1 + 16);
            }
#pragma unroll
            for (int mt = 0; mt < 2; mt++)
#pragma unroll
                for (int nt = 0; nt < 8; nt++) {
                    mma16816(d[mt][nt], ah[mt], bh[nt]);
                    mma16816(d[mt][nt], al[mt], bh[nt]);
                    mma16816(d[mt][nt], ah[mt], bl[nt]);
                }
        }
    }

    // epilogue: Yt[col][o]
#pragma unroll
    for (int mt = 0; mt < 2; mt++) {
        int r = oBase + wm * 32 + mt * 16 + l4;
#pragma unroll
        for (int nt = 0; nt < 8; nt++) {
            int c = colBase + wn * 64 + nt * 8 + lm4 * 2;
            g_Yt[(size_t)c * CC + r]           = d[mt][nt][0];
            g_Yt[(size_t)(c + 1) * CC + r]     = d[mt][nt][1];
            g_Yt[(size_t)c * CC + r + 8]       = d[mt][nt][2];
            g_Yt[(size_t)(c + 1) * CC + r + 8] = d[mt][nt][3];
        }
    }
}

// ---------------------------------------------------------------------------
// Kernel 5: bias + BN + ReLU + residual + LayerNorm(H=16)
// ---------------------------------------------------------------------------
__global__ void k_final(const float* __restrict__ x,
                        const float* __restrict__ conv_b,
                        const float* __restrict__ bn_g, const float* __restrict__ bn_b,
                        const float* __restrict__ bn_m, const float* __restrict__ bn_v,
                        const float* __restrict__ ln_g, const float* __restrict__ ln_b,
                        float* __restrict__ out) {
    int bs = blockIdx.x, n = threadIdx.x;
    size_t base = (size_t)bs * CC + n * HH;
    size_t obase = (size_t)n * HH;

    float v[HH];
#pragma unroll
    for (int h = 0; h < HH; h += 4) {
        float4 y = *(const float4*)&g_Yt[base + h];
        float4 cb = *(const float4*)&conv_b[obase + h];
        float4 bm = *(const float4*)&bn_m[obase + h];
        float4 bvr = *(const float4*)&bn_v[obase + h];
        float4 bg = *(const float4*)&bn_g[obase + h];
        float4 bb = *(const float4*)&bn_b[obase + h];
        float4 xr = *(const float4*)&x[base + h];
        float yy[4] = {y.x, y.y, y.z, y.w};
        float cbv[4] = {cb.x, cb.y, cb.z, cb.w};
        float bmv[4] = {bm.x, bm.y, bm.z, bm.w};
        float bvv[4] = {bvr.x, bvr.y, bvr.z, bvr.w};
        float bgv[4] = {bg.x, bg.y, bg.z, bg.w};
        float bbv[4] = {bb.x, bb.y, bb.z, bb.w};
        float xv[4] = {xr.x, xr.y, xr.z, xr.w};
#pragma unroll
        for (int q = 0; q < 4; q++) {
            float val = yy[q] + cbv[q];
            val = (val - bmv[q]) * rsqrtf(bvv[q] + EPS) * bgv[q] + bbv[q];
            val = fmaxf(val, 0.0f);
            v[h + q] = val + xv[q];
        }
    }

    float mu = 0.0f;
#pragma unroll
    for (int h = 0; h < HH; h++) mu += v[h];
    mu *= (1.0f / HH);
    float var = 0.0f;
#pragma unroll
    for (int h = 0; h < HH; h++) { float dd = v[h] - mu; var += dd * dd; }
    var *= (1.0f / HH);
    float is = rsqrtf(var + EPS);

#pragma unroll
    for (int h = 0; h < HH; h++)
        out[base + h] = (v[h] - mu) * is * ln_g[h] + ln_b[h];
}

// ---------------------------------------------------------------------------
extern "C" void kernel_launch(void* const* d_in, const int* in_sizes, int n_in,
                              void* d_out, int out_size) {
    const float* x      = (const float*)d_in[0];
    const float* adj    = (const float*)d_in[1];
    const float* W      = (const float*)d_in[2];
    const float* a1     = (const float*)d_in[3];
    const float* a2     = (const float*)d_in[4];
    const float* conv_w = (const float*)d_in[5];
    const float* conv_b = (const float*)d_in[6];
    const float* bn_g   = (const float*)d_in[7];
    const float* bn_b   = (const float*)d_in[8];
    const float* bn_m   = (const float*)d_in[9];
    const float* bn_v   = (const float*)d_in[10];
    const float* ln_g   = (const float*)d_in[11];
    const float* ln_b   = (const float*)d_in[12];
    float* out = (float*)d_out;

    cudaFuncSetAttribute(k_conv_mma, cudaFuncAttributeMaxDynamicSharedMemorySize, SMEM_DYN);

    k_mask<<<8, 256>>>(adj);
    k_wh<<<512, 256>>>(x, W, a1, a2);
    k_attn<<<512, 256>>>();
    k_splitw<<<49152, 256>>>(conv_w);
    k_buildB<<<512, 256>>>();
    k_conv_mma<<<dim3(4, 32), 256, SMEM_DYN>>>();
    k_final<<<512, 256>>>(x, conv_b, bn_g, bn_b, bn_m, bn_v, ln_g, ln_b, out);
}